// round 2
// baseline (speedup 1.0000x reference)
#include <cuda_runtime.h>
#include <cuda_bf16.h>

// Problem constants
#define BB 4
#define SSEQ 1024
#define IDIM 4096
#define RRK 512
#define RPD 64
#define HHD 32
#define DDH 128
#define NTOK (BB*SSEQ)          // 4096 tokens
#define EPSF 1.1920929e-07f

// ---------------- scratch layout (single __device__ array, no allocs) ------
static constexpr long O_DKV  = 0;                              // NTOK*576
static constexpr long O_CKV  = O_DKV  + (long)NTOK*576;        // NTOK*512
static constexpr long O_CKVT = O_CKV  + (long)NTOK*512;        // B*512*1024
static constexpr long O_KR   = O_CKVT + (long)BB*512*1024;     // NTOK*64
static constexpr long O_KRT  = O_KR   + (long)NTOK*64;         // B*64*1024
static constexpr long O_CQP  = O_KRT  + (long)BB*64*1024;      // NTOK*512
static constexpr long O_CQ   = O_CQP  + (long)NTOK*512;        // NTOK*512
static constexpr long O_Q    = O_CQ   + (long)NTOK*512;        // NTOK*4096
static constexpr long O_QRP  = O_Q    + (long)NTOK*4096;       // NTOK*64
static constexpr long O_QR   = O_QRP  + (long)NTOK*64;         // NTOK*64
static constexpr long O_G    = O_QR   + (long)NTOK*64;         // B*512*512
static constexpr long O_T1   = O_G    + (long)BB*512*512;      // B*H*128*512
static constexpr long O_W2T  = O_T1   + (long)BB*HHD*128*512;  // B*H*128*128
static constexpr long O_KCT  = O_W2T  + (long)BB*HHD*128*128;  // B*512*64
static constexpr long O_RA   = O_KCT  + (long)BB*512*64;       // NTOK*512
static constexpr long O_OHD  = O_RA   + (long)NTOK*512;        // NTOK*4096
static constexpr long SCRATCH_TOTAL = O_OHD + (long)NTOK*4096;

__device__ float g_scratch[SCRATCH_TOTAL];

// ---------------- SGEMM: C = A(MxK) * B(NxK)^T (+bias)(+=) -----------------
// 128x128x16 tile, 256 threads, 8x8 microkernel via 2x(4-row) x 2x(4-col)
// float4 fragments, double-buffered smem, one __syncthreads per K-tile.
// Batched via blockIdx.z decomposed as z1 = z / bz2n, z2 = z % bz2n.
#define BM 128
#define BN 128
#define BKK 16

__global__ void __launch_bounds__(256)
sgemm_nt(int M, int N, int K,
         const float* __restrict__ A, int lda, long sA1, long sA2,
         const float* __restrict__ B, int ldb, long sB1, long sB2,
         float* __restrict__ C, int ldc, long sC1, long sC2,
         int bz2n,
         const float* __restrict__ bias,
         int accumulate)
{
    __shared__ float As[2][BKK][BM + 4];
    __shared__ float Bs[2][BKK][BN + 4];

    int z  = blockIdx.z;
    int z2 = z % bz2n;
    int z1 = z / bz2n;
    A += z1 * sA1 + z2 * sA2;
    B += z1 * sB1 + z2 * sB2;
    C += z1 * sC1 + z2 * sC2;

    int tid     = threadIdx.x;
    int block_m = blockIdx.y * BM;
    int block_n = blockIdx.x * BN;

    // Loaders: 256 threads cover a 128x16 tile with two float4 each.
    int r   = tid >> 2;           // 0..63
    int c4  = (tid & 3) * 4;      // 0,4,8,12
    int a_m0 = block_m + r, a_m1 = a_m0 + 64;
    int b_n0 = block_n + r, b_n1 = b_n0 + 64;
    bool av0 = a_m0 < M, av1 = a_m1 < M;
    bool bv0 = b_n0 < N, bv1 = b_n1 < N;
    const float* A0 = A + (long)(av0 ? a_m0 : 0) * lda + c4;
    const float* A1 = A + (long)(av1 ? a_m1 : 0) * lda + c4;
    const float* B0 = B + (long)(bv0 ? b_n0 : 0) * ldb + c4;
    const float* B1 = B + (long)(bv1 ? b_n1 : 0) * ldb + c4;

    // Compute mapping: 16x16 thread grid, each owns rows {ty*4..+3, +64},
    // cols {tx*4..+3, +64}.
    int ty = tid >> 4;            // 0..15
    int tx = tid & 15;            // 0..15

    float acc[8][8];
#pragma unroll
    for (int i = 0; i < 8; i++)
#pragma unroll
        for (int j = 0; j < 8; j++) acc[i][j] = 0.f;

    const float4 fz = make_float4(0.f, 0.f, 0.f, 0.f);

    // ---- preload tile 0 into buffer 0
    {
        float4 pa0 = av0 ? *(const float4*)A0 : fz;
        float4 pa1 = av1 ? *(const float4*)A1 : fz;
        float4 pb0 = bv0 ? *(const float4*)B0 : fz;
        float4 pb1 = bv1 ? *(const float4*)B1 : fz;
        As[0][c4+0][r]    = pa0.x; As[0][c4+1][r]    = pa0.y;
        As[0][c4+2][r]    = pa0.z; As[0][c4+3][r]    = pa0.w;
        As[0][c4+0][r+64] = pa1.x; As[0][c4+1][r+64] = pa1.y;
        As[0][c4+2][r+64] = pa1.z; As[0][c4+3][r+64] = pa1.w;
        Bs[0][c4+0][r]    = pb0.x; Bs[0][c4+1][r]    = pb0.y;
        Bs[0][c4+2][r]    = pb0.z; Bs[0][c4+3][r]    = pb0.w;
        Bs[0][c4+0][r+64] = pb1.x; Bs[0][c4+1][r+64] = pb1.y;
        Bs[0][c4+2][r+64] = pb1.z; Bs[0][c4+3][r+64] = pb1.w;
    }
    __syncthreads();

    int KT = K / BKK;
    int buf = 0;
    for (int kt = 0; kt < KT; kt++) {
        float4 pa0, pa1, pb0, pb1;
        bool more = (kt + 1 < KT);
        if (more) {
            long ko = (long)(kt + 1) * BKK;
            pa0 = av0 ? *(const float4*)(A0 + ko) : fz;
            pa1 = av1 ? *(const float4*)(A1 + ko) : fz;
            pb0 = bv0 ? *(const float4*)(B0 + ko) : fz;
            pb1 = bv1 ? *(const float4*)(B1 + ko) : fz;
        }

#pragma unroll
        for (int k = 0; k < BKK; k++) {
            float4 a0 = *(const float4*)&As[buf][k][ty * 4];
            float4 a1 = *(const float4*)&As[buf][k][ty * 4 + 64];
            float4 b0 = *(const float4*)&Bs[buf][k][tx * 4];
            float4 b1 = *(const float4*)&Bs[buf][k][tx * 4 + 64];
            float ar[8] = {a0.x, a0.y, a0.z, a0.w, a1.x, a1.y, a1.z, a1.w};
            float br[8] = {b0.x, b0.y, b0.z, b0.w, b1.x, b1.y, b1.z, b1.w};
#pragma unroll
            for (int i = 0; i < 8; i++)
#pragma unroll
                for (int j = 0; j < 8; j++)
                    acc[i][j] += ar[i] * br[j];
        }

        if (more) {
            int nb = buf ^ 1;
            As[nb][c4+0][r]    = pa0.x; As[nb][c4+1][r]    = pa0.y;
            As[nb][c4+2][r]    = pa0.z; As[nb][c4+3][r]    = pa0.w;
            As[nb][c4+0][r+64] = pa1.x; As[nb][c4+1][r+64] = pa1.y;
            As[nb][c4+2][r+64] = pa1.z; As[nb][c4+3][r+64] = pa1.w;
            Bs[nb][c4+0][r]    = pb0.x; Bs[nb][c4+1][r]    = pb0.y;
            Bs[nb][c4+2][r]    = pb0.z; Bs[nb][c4+3][r]    = pb0.w;
            Bs[nb][c4+0][r+64] = pb1.x; Bs[nb][c4+1][r+64] = pb1.y;
            Bs[nb][c4+2][r+64] = pb1.z; Bs[nb][c4+3][r+64] = pb1.w;
            __syncthreads();
            buf = nb;
        }
    }

    // ---- epilogue: float4 stores (all our N are multiples of 4)
#pragma unroll
    for (int hm = 0; hm < 2; hm++) {
#pragma unroll
        for (int im = 0; im < 4; im++) {
            int m = block_m + hm * 64 + ty * 4 + im;
            if (m >= M) continue;
#pragma unroll
            for (int hn = 0; hn < 2; hn++) {
                int n = block_n + hn * 64 + tx * 4;
                if (n >= N) continue;
                float4 v = make_float4(acc[hm*4+im][hn*4+0], acc[hm*4+im][hn*4+1],
                                       acc[hm*4+im][hn*4+2], acc[hm*4+im][hn*4+3]);
                if (bias) {
                    float4 bb = *(const float4*)(bias + n);
                    v.x += bb.x; v.y += bb.y; v.z += bb.z; v.w += bb.w;
                }
                long idx = (long)m * ldc + n;
                if (accumulate) {
                    float4 cc = *(const float4*)(C + idx);
                    v.x += cc.x; v.y += cc.y; v.z += cc.z; v.w += cc.w;
                }
                *(float4*)(C + idx) = v;
            }
        }
    }
}

// ---------------- block reduce helper --------------------------------------
__device__ __forceinline__ float block_reduce_sum(float v) {
    __shared__ float sm[32];
    int lane = threadIdx.x & 31;
    int w    = threadIdx.x >> 5;
#pragma unroll
    for (int o = 16; o; o >>= 1) v += __shfl_down_sync(0xffffffffu, v, o);
    if (lane == 0) sm[w] = v;
    __syncthreads();
    int nw = blockDim.x >> 5;
    v = (threadIdx.x < nw) ? sm[threadIdx.x] : 0.f;
    if (w == 0) {
#pragma unroll
        for (int o = 16; o; o >>= 1) v += __shfl_down_sync(0xffffffffu, v, o);
        if (lane == 0) sm[0] = v;
    }
    __syncthreads();
    return sm[0];
}

// ---------------- fused kv rmsnorm + rope key -------------------------------
__global__ void __launch_bounds__(256)
kv_fuse(const float* __restrict__ dkv, const float* __restrict__ kvw,
        const float* __restrict__ ch, const float* __restrict__ sh,
        float* __restrict__ ckv, float* __restrict__ kr)
{
    int row = blockIdx.x;          // 0..NTOK-1
    int s   = row % SSEQ;
    const float* v = dkv + (long)row * 576;

    float ss = 0.f;
    for (int i = threadIdx.x; i < RRK; i += blockDim.x) { float t = v[i]; ss += t * t; }
    float tot = block_reduce_sum(ss);
    float inv = rsqrtf(tot / (float)RRK + EPSF);
    for (int i = threadIdx.x; i < RRK; i += blockDim.x)
        ckv[(long)row * RRK + i] = v[i] * inv * kvw[i];

    if (threadIdx.x < 32) {
        int j = threadIdx.x;
        float c  = ch[s * 32 + j];
        float sn = sh[s * 32 + j];
        float x0 = v[RRK + j];
        float x1 = v[RRK + 32 + j];
        kr[(long)row * RPD + j]      = x0 * c - x1 * sn;
        kr[(long)row * RPD + 32 + j] = x1 * c + x0 * sn;
    }
}

// ---------------- rmsnorm (512 wide) ---------------------------------------
__global__ void __launch_bounds__(256)
rmsnorm512(const float* __restrict__ in, const float* __restrict__ w,
           float* __restrict__ out)
{
    int row = blockIdx.x;
    const float* v = in + (long)row * RRK;
    float ss = 0.f;
    for (int i = threadIdx.x; i < RRK; i += blockDim.x) { float t = v[i]; ss += t * t; }
    float tot = block_reduce_sum(ss);
    float inv = rsqrtf(tot / (float)RRK + EPSF);
    for (int i = threadIdx.x; i < RRK; i += blockDim.x)
        out[(long)row * RRK + i] = v[i] * inv * w[i];
}

// ---------------- rope (64 wide) -------------------------------------------
__global__ void __launch_bounds__(32)
rope64(const float* __restrict__ in, const float* __restrict__ ch,
       const float* __restrict__ sh, float* __restrict__ out)
{
    int row = blockIdx.x;
    int s   = row % SSEQ;
    int j   = threadIdx.x;      // 0..31
    float c  = ch[s * 32 + j];
    float sn = sh[s * 32 + j];
    float x0 = in[(long)row * RPD + j];
    float x1 = in[(long)row * RPD + 32 + j];
    out[(long)row * RPD + j]      = x0 * c - x1 * sn;
    out[(long)row * RPD + 32 + j] = x1 * c + x0 * sn;
}

// ---------------- transpose (rows x cols -> cols x rows), batched via z ----
__global__ void __launch_bounds__(256)
transpose_k(const float* __restrict__ in, float* __restrict__ out,
            int rows, int cols)
{
    __shared__ float tile[32][33];
    long boff = (long)blockIdx.z * rows * cols;
    const float* ip = in + boff;
    float* op = out + boff;

    int x = blockIdx.x * 32 + threadIdx.x;  // col
    int y0 = blockIdx.y * 32;               // row base
    int ty = threadIdx.y;                    // 0..7
#pragma unroll
    for (int j = 0; j < 32; j += 8) {
        int y = y0 + ty + j;
        if (y < rows && x < cols)
            tile[ty + j][threadIdx.x] = ip[(long)y * cols + x];
    }
    __syncthreads();
    int xo = blockIdx.y * 32 + threadIdx.x; // row index in source = col in dst
    int y1 = blockIdx.x * 32;
#pragma unroll
    for (int j = 0; j < 32; j += 8) {
        int y = y1 + ty + j;
        if (y < cols && xo < rows)
            op[(long)y * rows + xo] = tile[threadIdx.x][ty + j];
    }
}

// ---------------- host orchestration ---------------------------------------
static inline void launch_gemm(int M, int N, int K,
                               const float* A, int lda, long sA1, long sA2,
                               const float* B, int ldb, long sB1, long sB2,
                               float* C, int ldc, long sC1, long sC2,
                               int Z, int bz2n,
                               const float* bias, int accumulate)
{
    dim3 grid((N + BN - 1) / BN, (M + BM - 1) / BM, Z);
    sgemm_nt<<<grid, 256>>>(M, N, K, A, lda, sA1, sA2, B, ldb, sB1, sB2,
                            C, ldc, sC1, sC2, bz2n, bias, accumulate);
}

extern "C" void kernel_launch(void* const* d_in, const int* in_sizes, int n_in,
                              void* d_out, int out_size)
{
    const float* x      = (const float*)d_in[0];
    const float* ch     = (const float*)d_in[1];
    const float* sh     = (const float*)d_in[2];
    const float* mask   = (const float*)d_in[3];
    const float* w_dkv  = (const float*)d_in[4];
    const float* b_dkv  = (const float*)d_in[5];
    const float* kvw    = (const float*)d_in[6];
    const float* w_dq   = (const float*)d_in[7];
    const float* b_dq   = (const float*)d_in[8];
    const float* qnw    = (const float*)d_in[9];
    const float* w_uq   = (const float*)d_in[10];
    const float* b_uq   = (const float*)d_in[11];
    const float* w_qr   = (const float*)d_in[12];
    const float* b_qr   = (const float*)d_in[13];
    const float* w_uk   = (const float*)d_in[14];
    const float* w_uv   = (const float*)d_in[15];
    const float* w_o    = (const float*)d_in[16];
    const float* b_o    = (const float*)d_in[17];
    float* out = (float*)d_out;

    float* scr = nullptr;
    cudaGetSymbolAddress((void**)&scr, g_scratch);

    float* dkv  = scr + O_DKV;
    float* ckv  = scr + O_CKV;
    float* ckvT = scr + O_CKVT;
    float* kr   = scr + O_KR;
    float* krT  = scr + O_KRT;
    float* cqp  = scr + O_CQP;
    float* cq   = scr + O_CQ;
    float* q    = scr + O_Q;
    float* qrp  = scr + O_QRP;
    float* qr   = scr + O_QR;
    float* G    = scr + O_G;
    float* T1   = scr + O_T1;
    float* W2T  = scr + O_W2T;
    float* kcT  = scr + O_KCT;
    float* ra   = scr + O_RA;
    float* ohd  = scr + O_OHD;

    // 1) dkv = x @ w_dkv^T + b        (4096 x 576 x 4096)
    launch_gemm(NTOK, RRK + RPD, IDIM, x, IDIM, 0, 0, w_dkv, IDIM, 0, 0,
                dkv, RRK + RPD, 0, 0, 1, 1, b_dkv, 0);

    // 2) c_kv = rmsnorm(dkv[:,:512]); k_r = rope(dkv[:,512:])
    kv_fuse<<<NTOK, 256>>>(dkv, kvw, ch, sh, ckv, kr);

    // 3) transposes per batch: ckvT (512x1024), krT (64x1024)
    {
        dim3 g1(RRK / 32, SSEQ / 32, BB);
        transpose_k<<<g1, dim3(32, 8)>>>(ckv, ckvT, SSEQ, RRK);
        dim3 g2(RPD / 32, SSEQ / 32, BB);
        transpose_k<<<g2, dim3(32, 8)>>>(kr, krT, SSEQ, RPD);
    }

    // 4) cq_pre = x @ w_dq^T + b      (4096 x 512 x 4096)
    launch_gemm(NTOK, RRK, IDIM, x, IDIM, 0, 0, w_dq, IDIM, 0, 0,
                cqp, RRK, 0, 0, 1, 1, b_dq, 0);

    // 5) c_q = rmsnorm(cq_pre)
    rmsnorm512<<<NTOK, 256>>>(cqp, qnw, cq);

    // 6) q = c_q @ w_uq^T + b         (4096 x 4096 x 512)
    launch_gemm(NTOK, HHD * DDH, RRK, cq, RRK, 0, 0, w_uq, RRK, 0, 0,
                q, HHD * DDH, 0, 0, 1, 1, b_uq, 0);

    // 7) qr_pre = c_q @ w_qr^T + b    (4096 x 64 x 512)
    launch_gemm(NTOK, RPD, RRK, cq, RRK, 0, 0, w_qr, RRK, 0, 0,
                qrp, RPD, 0, 0, 1, 1, b_qr, 0);

    // 8) q_r = rope(qr_pre)
    rope64<<<NTOK, 32>>>(qrp, ch, sh, qr);

    // 9) G_b = ckvT @ ckvT^T          (z=4: 512 x 512 x 1024)
    launch_gemm(RRK, RRK, SSEQ,
                ckvT, SSEQ, (long)RRK * SSEQ, 0,
                ckvT, SSEQ, (long)RRK * SSEQ, 0,
                G, RRK, (long)RRK * RRK, 0,
                BB, 1, nullptr, 0);

    // 10) T1[b,h] = w_uv_h @ G_b      (z=128: 128 x 512 x 512)  (G symmetric)
    launch_gemm(DDH, RRK, RRK,
                w_uv, RRK, 0, (long)DDH * RRK,
                G,    RRK, (long)RRK * RRK, 0,
                T1,   RRK, (long)HHD * DDH * RRK, (long)DDH * RRK,
                BB * HHD, HHD, nullptr, 0);

    // 11) W2T[b,h] = T1 @ w_uk_h^T    (z=128: 128 x 128 x 512)
    launch_gemm(DDH, DDH, RRK,
                T1,   RRK, (long)HHD * DDH * RRK, (long)DDH * RRK,
                w_uk, RRK, 0, (long)DDH * RRK,
                W2T,  DDH, (long)HHD * DDH * DDH, (long)DDH * DDH,
                BB * HHD, HHD, nullptr, 0);

    // 12) ra = mask @ ckv_b           (z=4: 1024 x 512 x 1024)  [mask shared]
    launch_gemm(SSEQ, RRK, SSEQ,
                mask, SSEQ, 0, 0,
                ckvT, SSEQ, (long)RRK * SSEQ, 0,
                ra, RRK, (long)SSEQ * RRK, 0,
                BB, 1, nullptr, 0);

    // 13) kcT[b] = ckvT_b @ krT_b^T   (z=4: 512 x 64 x 1024)
    launch_gemm(RRK, RPD, SSEQ,
                ckvT, SSEQ, (long)RRK * SSEQ, 0,
                krT,  SSEQ, (long)RPD * SSEQ, 0,
                kcT, RPD, (long)RRK * RPD, 0,
                BB, 1, nullptr, 0);

    // 14) ra += q_r @ kcT^T           (z=4: 1024 x 512 x 64)
    launch_gemm(SSEQ, RRK, RPD,
                qr,  RPD, (long)SSEQ * RPD, 0,
                kcT, RPD, (long)RRK * RPD, 0,
                ra, RRK, (long)SSEQ * RRK, 0,
                BB, 1, nullptr, 1);

    // 15) out_hd = ra @ w_uv^T        (4096 x 4096 x 512)
    launch_gemm(NTOK, HHD * DDH, RRK, ra, RRK, 0, 0, w_uv, RRK, 0, 0,
                ohd, HHD * DDH, 0, 0, 1, 1, nullptr, 0);

    // 16) out_hd[b,:,hD:(h+1)D] += q[b,:,hD:+D] @ W2T[b,h]^T  (z=128: 1024x128x128)
    launch_gemm(SSEQ, DDH, DDH,
                q,   HHD * DDH, (long)SSEQ * HHD * DDH, (long)DDH,
                W2T, DDH, (long)HHD * DDH * DDH, (long)DDH * DDH,
                ohd, HHD * DDH, (long)SSEQ * HHD * DDH, (long)DDH,
                BB * HHD, HHD, nullptr, 1);

    // 17) out = out_hd @ w_o^T + b_o  (4096 x 4096 x 4096)
    launch_gemm(NTOK, IDIM, IDIM, ohd, IDIM, 0, 0, w_o, IDIM, 0, 0,
                out, IDIM, 0, 0, 1, 1, b_o, 0);
}

// round 6
// speedup vs baseline: 2.5076x; 2.5076x over previous
#include <cuda_runtime.h>
#include <cuda_bf16.h>
#include <cstdint>

// Problem constants
#define BB 4
#define SSEQ 1024
#define IDIM 4096
#define RRK 512
#define RPD 64
#define HHD 32
#define DDH 128
#define NTOK (BB*SSEQ)          // 4096 tokens
#define EPSF 1.1920929e-07f

// ---------------- scratch layout (single __device__ array, no allocs) ------
static constexpr long O_DKV  = 0;                              // NTOK*576
static constexpr long O_CKV  = O_DKV  + (long)NTOK*576;        // NTOK*512
static constexpr long O_CKVT = O_CKV  + (long)NTOK*512;        // B*512*1024
static constexpr long O_KR   = O_CKVT + (long)BB*512*1024;     // NTOK*64
static constexpr long O_KRT  = O_KR   + (long)NTOK*64;         // B*64*1024
static constexpr long O_CQP  = O_KRT  + (long)BB*64*1024;      // NTOK*512
static constexpr long O_CQ   = O_CQP  + (long)NTOK*512;        // NTOK*512
static constexpr long O_Q    = O_CQ   + (long)NTOK*512;        // NTOK*4096
static constexpr long O_QRP  = O_Q    + (long)NTOK*4096;       // NTOK*64
static constexpr long O_QR   = O_QRP  + (long)NTOK*64;         // NTOK*64
static constexpr long O_G    = O_QR   + (long)NTOK*64;         // B*512*512
static constexpr long O_T1   = O_G    + (long)BB*512*512;      // B*H*128*512
static constexpr long O_W2T  = O_T1   + (long)BB*HHD*128*512;  // B*H*128*128
static constexpr long O_KCT  = O_W2T  + (long)BB*HHD*128*128;  // B*512*64
static constexpr long O_RA   = O_KCT  + (long)BB*512*64;       // NTOK*512
static constexpr long O_OHD  = O_RA   + (long)NTOK*512;        // NTOK*4096
static constexpr long SCRATCH_TOTAL = O_OHD + (long)NTOK*4096;

__device__ float g_scratch[SCRATCH_TOTAL];

// ---------------- bf16x3 tensor-core GEMM: C = A(MxK)*B(NxK)^T -------------
// Each fp32 operand is split x = hi + lo (both bf16). Products hi*hi + hi*lo
// + lo*hi are accumulated in fp32 via mma.sync.m16n8k16 -> ~2^-16 relative
// precision per GEMM. Tile 128x128x32, 8 warps (2x4), warp tile 64x32.
// smem rows padded to 40 bf16 (80B) -> ldmatrix conflict-free.
// Batched via blockIdx.z decomposed as z1 = z / bz2n, z2 = z % bz2n.

__device__ __forceinline__ void ldsm4(uint32_t& r0, uint32_t& r1,
                                      uint32_t& r2, uint32_t& r3,
                                      const void* p)
{
    uint32_t addr = (uint32_t)__cvta_generic_to_shared(p);
    asm volatile("ldmatrix.sync.aligned.m8n8.x4.shared.b16 {%0,%1,%2,%3},[%4];"
                 : "=r"(r0), "=r"(r1), "=r"(r2), "=r"(r3) : "r"(addr));
}

__device__ __forceinline__ void mma_bf16(float* d, const uint32_t* a,
                                         const uint32_t* b)
{
    asm volatile(
        "mma.sync.aligned.m16n8k16.row.col.f32.bf16.bf16.f32 "
        "{%0,%1,%2,%3},{%4,%5,%6,%7},{%8,%9},{%0,%1,%2,%3};"
        : "+f"(d[0]), "+f"(d[1]), "+f"(d[2]), "+f"(d[3])
        : "r"(a[0]), "r"(a[1]), "r"(a[2]), "r"(a[3]), "r"(b[0]), "r"(b[1]));
}

// split a float4 into hi/lo bf16 quads and store (8B each)
__device__ __forceinline__ void split_store(__nv_bfloat16* hi,
                                            __nv_bfloat16* lo, float4 v)
{
    __nv_bfloat16 h0 = __float2bfloat16_rn(v.x);
    __nv_bfloat16 h1 = __float2bfloat16_rn(v.y);
    __nv_bfloat16 h2 = __float2bfloat16_rn(v.z);
    __nv_bfloat16 h3 = __float2bfloat16_rn(v.w);
    __nv_bfloat162 hA; hA.x = h0; hA.y = h1;
    __nv_bfloat162 hB; hB.x = h2; hB.y = h3;
    *(__nv_bfloat162*)(hi + 0) = hA;
    *(__nv_bfloat162*)(hi + 2) = hB;
    __nv_bfloat162 lA, lB;
    lA.x = __float2bfloat16_rn(v.x - __bfloat162float(h0));
    lA.y = __float2bfloat16_rn(v.y - __bfloat162float(h1));
    lB.x = __float2bfloat16_rn(v.z - __bfloat162float(h2));
    lB.y = __float2bfloat16_rn(v.w - __bfloat162float(h3));
    *(__nv_bfloat162*)(lo + 0) = lA;
    *(__nv_bfloat162*)(lo + 2) = lB;
}

#define LDP 40   // smem row pitch in bf16 (80 bytes)

__global__ void __launch_bounds__(256)
bmma_nt(int M, int N, int K,
        const float* __restrict__ A, int lda, long sA1, long sA2,
        const float* __restrict__ B, int ldb, long sB1, long sB2,
        float* __restrict__ C, int ldc, long sC1, long sC2,
        int bz2n,
        const float* __restrict__ bias,
        int accumulate)
{
    __shared__ __align__(16) __nv_bfloat16 Ash[2][128][LDP];  // [hi/lo][m][k]
    __shared__ __align__(16) __nv_bfloat16 Bsh[2][128][LDP];  // [hi/lo][n][k]

    int z  = blockIdx.z;
    int z2 = z % bz2n;
    int z1 = z / bz2n;
    A += z1 * sA1 + z2 * sA2;
    B += z1 * sB1 + z2 * sB2;
    C += z1 * sC1 + z2 * sC2;

    int tid  = threadIdx.x;
    int lane = tid & 31;
    int wid  = tid >> 5;
    int wm   = wid >> 2;        // 0..1  -> m offset wm*64
    int wn   = wid & 3;         // 0..3  -> n offset wn*32
    int bm   = blockIdx.y * 128;
    int bn   = blockIdx.x * 128;

    // loader geometry: 8 threads cover one row's 32 k-floats, 32 rows/warp pass
    int lk = (tid & 7) * 4;     // k offset 0..28
    int lr = tid >> 3;          // row 0..31

    // ldmatrix lane geometry
    int g   = lane >> 3;
    int r8  = lane & 7;
    int lmr = (g & 1) * 8 + r8; // row within 16-row frag
    int lmk = (g >> 1) * 8;     // k offset within 16

    float acc[4][4][4];
#pragma unroll
    for (int i = 0; i < 4; i++)
#pragma unroll
        for (int j = 0; j < 4; j++)
#pragma unroll
            for (int e = 0; e < 4; e++) acc[i][j][e] = 0.f;

    const float4 fz = make_float4(0.f, 0.f, 0.f, 0.f);

    for (int k0 = 0; k0 < K; k0 += 32) {
        // ---- fill smem (load fp32, split to hi/lo bf16)
#pragma unroll
        for (int i = 0; i < 4; i++) {
            int mr = lr + i * 32;
            int gm = bm + mr;
            float4 va = (gm < M) ? *(const float4*)(A + (long)gm * lda + k0 + lk) : fz;
            split_store(&Ash[0][mr][lk], &Ash[1][mr][lk], va);
            int gn = bn + mr;
            float4 vb = (gn < N) ? *(const float4*)(B + (long)gn * ldb + k0 + lk) : fz;
            split_store(&Bsh[0][mr][lk], &Bsh[1][mr][lk], vb);
        }
        __syncthreads();

        // ---- compute: two k16 chunks
#pragma unroll
        for (int kc = 0; kc < 2; kc++) {
            uint32_t bh[4][2], bl[4][2];
#pragma unroll
            for (int t = 0; t < 2; t++) {
                const __nv_bfloat16* ph = &Bsh[0][wn * 32 + t * 16 + lmr][kc * 16 + lmk];
                ldsm4(bh[2*t][0], bh[2*t+1][0], bh[2*t][1], bh[2*t+1][1], ph);
                const __nv_bfloat16* pl = &Bsh[1][wn * 32 + t * 16 + lmr][kc * 16 + lmk];
                ldsm4(bl[2*t][0], bl[2*t+1][0], bl[2*t][1], bl[2*t+1][1], pl);
            }
#pragma unroll
            for (int mf = 0; mf < 4; mf++) {
                uint32_t ah[4], al[4];
                const __nv_bfloat16* pa = &Ash[0][wm * 64 + mf * 16 + lmr][kc * 16 + lmk];
                ldsm4(ah[0], ah[1], ah[2], ah[3], pa);
                const __nv_bfloat16* pb = &Ash[1][wm * 64 + mf * 16 + lmr][kc * 16 + lmk];
                ldsm4(al[0], al[1], al[2], al[3], pb);
#pragma unroll
                for (int nf = 0; nf < 4; nf++) {
                    mma_bf16(acc[mf][nf], ah, bh[nf]);   // hi*hi
                    mma_bf16(acc[mf][nf], ah, bl[nf]);   // hi*lo
                    mma_bf16(acc[mf][nf], al, bh[nf]);   // lo*hi
                }
            }
        }
        __syncthreads();
    }

    // ---- epilogue: d-frag rows (lane>>2, +8), cols 2*(lane&3)+{0,1}
#pragma unroll
    for (int mf = 0; mf < 4; mf++) {
#pragma unroll
        for (int nf = 0; nf < 4; nf++) {
            int r0 = bm + wm * 64 + mf * 16 + (lane >> 2);
            int c  = bn + wn * 32 + nf * 8 + (lane & 3) * 2;
            if (c < N) {
                float b0 = bias ? bias[c]     : 0.f;
                float b1 = bias ? bias[c + 1] : 0.f;
#pragma unroll
                for (int h = 0; h < 2; h++) {
                    int r = r0 + h * 8;
                    if (r < M) {
                        long idx = (long)r * ldc + c;
                        float v0 = acc[mf][nf][2*h + 0] + b0;
                        float v1 = acc[mf][nf][2*h + 1] + b1;
                        if (accumulate) { v0 += C[idx]; v1 += C[idx + 1]; }
                        C[idx]     = v0;
                        C[idx + 1] = v1;
                    }
                }
            }
        }
    }
}

// ---------------- block reduce helper --------------------------------------
__device__ __forceinline__ float block_reduce_sum(float v) {
    __shared__ float sm[32];
    int lane = threadIdx.x & 31;
    int w    = threadIdx.x >> 5;
#pragma unroll
    for (int o = 16; o; o >>= 1) v += __shfl_down_sync(0xffffffffu, v, o);
    if (lane == 0) sm[w] = v;
    __syncthreads();
    int nw = blockDim.x >> 5;
    v = (threadIdx.x < nw) ? sm[threadIdx.x] : 0.f;
    if (w == 0) {
#pragma unroll
        for (int o = 16; o; o >>= 1) v += __shfl_down_sync(0xffffffffu, v, o);
        if (lane == 0) sm[0] = v;
    }
    __syncthreads();
    return sm[0];
}

// ---------------- fused kv rmsnorm + rope key -------------------------------
__global__ void __launch_bounds__(256)
kv_fuse(const float* __restrict__ dkv, const float* __restrict__ kvw,
        const float* __restrict__ ch, const float* __restrict__ sh,
        float* __restrict__ ckv, float* __restrict__ kr)
{
    int row = blockIdx.x;          // 0..NTOK-1
    int s   = row % SSEQ;
    const float* v = dkv + (long)row * 576;

    float ss = 0.f;
    for (int i = threadIdx.x; i < RRK; i += blockDim.x) { float t = v[i]; ss += t * t; }
    float tot = block_reduce_sum(ss);
    float inv = rsqrtf(tot / (float)RRK + EPSF);
    for (int i = threadIdx.x; i < RRK; i += blockDim.x)
        ckv[(long)row * RRK + i] = v[i] * inv * kvw[i];

    if (threadIdx.x < 32) {
        int j = threadIdx.x;
        float c  = ch[s * 32 + j];
        float sn = sh[s * 32 + j];
        float x0 = v[RRK + j];
        float x1 = v[RRK + 32 + j];
        kr[(long)row * RPD + j]      = x0 * c - x1 * sn;
        kr[(long)row * RPD + 32 + j] = x1 * c + x0 * sn;
    }
}

// ---------------- rmsnorm (512 wide) ---------------------------------------
__global__ void __launch_bounds__(256)
rmsnorm512(const float* __restrict__ in, const float* __restrict__ w,
           float* __restrict__ out)
{
    int row = blockIdx.x;
    const float* v = in + (long)row * RRK;
    float ss = 0.f;
    for (int i = threadIdx.x; i < RRK; i += blockDim.x) { float t = v[i]; ss += t * t; }
    float tot = block_reduce_sum(ss);
    float inv = rsqrtf(tot / (float)RRK + EPSF);
    for (int i = threadIdx.x; i < RRK; i += blockDim.x)
        out[(long)row * RRK + i] = v[i] * inv * w[i];
}

// ---------------- rope (64 wide) -------------------------------------------
__global__ void __launch_bounds__(32)
rope64(const float* __restrict__ in, const float* __restrict__ ch,
       const float* __restrict__ sh, float* __restrict__ out)
{
    int row = blockIdx.x;
    int s   = row % SSEQ;
    int j   = threadIdx.x;      // 0..31
    float c  = ch[s * 32 + j];
    float sn = sh[s * 32 + j];
    float x0 = in[(long)row * RPD + j];
    float x1 = in[(long)row * RPD + 32 + j];
    out[(long)row * RPD + j]      = x0 * c - x1 * sn;
    out[(long)row * RPD + 32 + j] = x1 * c + x0 * sn;
}

// ---------------- transpose (rows x cols -> cols x rows), batched via z ----
__global__ void __launch_bounds__(256)
transpose_k(const float* __restrict__ in, float* __restrict__ out,
            int rows, int cols)
{
    __shared__ float tile[32][33];
    long boff = (long)blockIdx.z * rows * cols;
    const float* ip = in + boff;
    float* op = out + boff;

    int x = blockIdx.x * 32 + threadIdx.x;  // col
    int y0 = blockIdx.y * 32;               // row base
    int ty = threadIdx.y;                    // 0..7
#pragma unroll
    for (int j = 0; j < 32; j += 8) {
        int y = y0 + ty + j;
        if (y < rows && x < cols)
            tile[ty + j][threadIdx.x] = ip[(long)y * cols + x];
    }
    __syncthreads();
    int xo = blockIdx.y * 32 + threadIdx.x; // row index in source = col in dst
    int y1 = blockIdx.x * 32;
#pragma unroll
    for (int j = 0; j < 32; j += 8) {
        int y = y1 + ty + j;
        if (y < cols && xo < rows)
            op[(long)y * rows + xo] = tile[threadIdx.x][ty + j];
    }
}

// ---------------- host orchestration ---------------------------------------
static inline void launch_gemm(int M, int N, int K,
                               const float* A, int lda, long sA1, long sA2,
                               const float* B, int ldb, long sB1, long sB2,
                               float* C, int ldc, long sC1, long sC2,
                               int Z, int bz2n,
                               const float* bias, int accumulate)
{
    dim3 grid((N + 127) / 128, (M + 127) / 128, Z);
    bmma_nt<<<grid, 256>>>(M, N, K, A, lda, sA1, sA2, B, ldb, sB1, sB2,
                           C, ldc, sC1, sC2, bz2n, bias, accumulate);
}

extern "C" void kernel_launch(void* const* d_in, const int* in_sizes, int n_in,
                              void* d_out, int out_size)
{
    const float* x      = (const float*)d_in[0];
    const float* ch     = (const float*)d_in[1];
    const float* sh     = (const float*)d_in[2];
    const float* mask   = (const float*)d_in[3];
    const float* w_dkv  = (const float*)d_in[4];
    const float* b_dkv  = (const float*)d_in[5];
    const float* kvw    = (const float*)d_in[6];
    const float* w_dq   = (const float*)d_in[7];
    const float* b_dq   = (const float*)d_in[8];
    const float* qnw    = (const float*)d_in[9];
    const float* w_uq   = (const float*)d_in[10];
    const float* b_uq   = (const float*)d_in[11];
    const float* w_qr   = (const float*)d_in[12];
    const float* b_qr   = (const float*)d_in[13];
    const float* w_uk   = (const float*)d_in[14];
    const float* w_uv   = (const float*)d_in[15];
    const float* w_o    = (const float*)d_in[16];
    const float* b_o    = (const float*)d_in[17];
    float* out = (float*)d_out;

    float* scr = nullptr;
    cudaGetSymbolAddress((void**)&scr, g_scratch);

    float* dkv  = scr + O_DKV;
    float* ckv  = scr + O_CKV;
    float* ckvT = scr + O_CKVT;
    float* kr   = scr + O_KR;
    float* krT  = scr + O_KRT;
    float* cqp  = scr + O_CQP;
    float* cq   = scr + O_CQ;
    float* q    = scr + O_Q;
    float* qrp  = scr + O_QRP;
    float* qr   = scr + O_QR;
    float* G    = scr + O_G;
    float* T1   = scr + O_T1;
    float* W2T  = scr + O_W2T;
    float* kcT  = scr + O_KCT;
    float* ra   = scr + O_RA;
    float* ohd  = scr + O_OHD;

    // launch 0) dkv = x @ w_dkv^T + b        (4096 x 576 x 4096)
    launch_gemm(NTOK, RRK + RPD, IDIM, x, IDIM, 0, 0, w_dkv, IDIM, 0, 0,
                dkv, RRK + RPD, 0, 0, 1, 1, b_dkv, 0);

    // launch 1) cq_pre = x @ w_dq^T + b      (4096 x 512 x 4096)
    launch_gemm(NTOK, RRK, IDIM, x, IDIM, 0, 0, w_dq, IDIM, 0, 0,
                cqp, RRK, 0, 0, 1, 1, b_dq, 0);

    // launch 2) c_kv = rmsnorm(dkv[:,:512]); k_r = rope(dkv[:,512:])
    kv_fuse<<<NTOK, 256>>>(dkv, kvw, ch, sh, ckv, kr);

    // launch 3) c_q = rmsnorm(cq_pre)
    rmsnorm512<<<NTOK, 256>>>(cqp, qnw, cq);

    // launch 4) ckvT (512x1024 per batch)
    {
        dim3 g1(RRK / 32, SSEQ / 32, BB);
        transpose_k<<<g1, dim3(32, 8)>>>(ckv, ckvT, SSEQ, RRK);
    }

    // launch 5) q = c_q @ w_uq^T + b         (4096 x 4096 x 512)  [profiled]
    launch_gemm(NTOK, HHD * DDH, RRK, cq, RRK, 0, 0, w_uq, RRK, 0, 0,
                q, HHD * DDH, 0, 0, 1, 1, b_uq, 0);

    // launch 6) krT (64x1024 per batch)
    {
        dim3 g2(RPD / 32, SSEQ / 32, BB);
        transpose_k<<<g2, dim3(32, 8)>>>(kr, krT, SSEQ, RPD);
    }

    // 7) qr_pre = c_q @ w_qr^T + b    (4096 x 64 x 512)
    launch_gemm(NTOK, RPD, RRK, cq, RRK, 0, 0, w_qr, RRK, 0, 0,
                qrp, RPD, 0, 0, 1, 1, b_qr, 0);

    // 8) q_r = rope(qr_pre)
    rope64<<<NTOK, 32>>>(qrp, ch, sh, qr);

    // 9) G_b = ckvT @ ckvT^T          (z=4: 512 x 512 x 1024)
    launch_gemm(RRK, RRK, SSEQ,
                ckvT, SSEQ, (long)RRK * SSEQ, 0,
                ckvT, SSEQ, (long)RRK * SSEQ, 0,
                G, RRK, (long)RRK * RRK, 0,
                BB, 1, nullptr, 0);

    // 10) T1[b,h] = w_uv_h @ G_b      (z=128: 128 x 512 x 512)  (G symmetric)
    launch_gemm(DDH, RRK, RRK,
                w_uv, RRK, 0, (long)DDH * RRK,
                G,    RRK, (long)RRK * RRK, 0,
                T1,   RRK, (long)HHD * DDH * RRK, (long)DDH * RRK,
                BB * HHD, HHD, nullptr, 0);

    // 11) W2T[b,h] = T1 @ w_uk_h^T    (z=128: 128 x 128 x 512)
    launch_gemm(DDH, DDH, RRK,
                T1,   RRK, (long)HHD * DDH * RRK, (long)DDH * RRK,
                w_uk, RRK, 0, (long)DDH * RRK,
                W2T,  DDH, (long)HHD * DDH * DDH, (long)DDH * DDH,
                BB * HHD, HHD, nullptr, 0);

    // 12) ra = mask @ ckv_b           (z=4: 1024 x 512 x 1024)  [mask shared]
    launch_gemm(SSEQ, RRK, SSEQ,
                mask, SSEQ, 0, 0,
                ckvT, SSEQ, (long)RRK * SSEQ, 0,
                ra, RRK, (long)SSEQ * RRK, 0,
                BB, 1, nullptr, 0);

    // 13) kcT[b] = ckvT_b @ krT_b^T   (z=4: 512 x 64 x 1024)
    launch_gemm(RRK, RPD, SSEQ,
                ckvT, SSEQ, (long)RRK * SSEQ, 0,
                krT,  SSEQ, (long)RPD * SSEQ, 0,
                kcT, RPD, (long)RRK * RPD, 0,
                BB, 1, nullptr, 0);

    // 14) ra += q_r @ kcT^T           (z=4: 1024 x 512 x 64)
    launch_gemm(SSEQ, RRK, RPD,
                qr,  RPD, (long)SSEQ * RPD, 0,
                kcT, RPD, (long)RRK * RPD, 0,
                ra, RRK, (long)SSEQ * RRK, 0,
                BB, 1, nullptr, 1);

    // 15) out_hd = ra @ w_uv^T        (4096 x 4096 x 512)
    launch_gemm(NTOK, HHD * DDH, RRK, ra, RRK, 0, 0, w_uv, RRK, 0, 0,
                ohd, HHD * DDH, 0, 0, 1, 1, nullptr, 0);

    // 16) out_hd[b,:,hD:(h+1)D] += q[b,:,hD:+D] @ W2T[b,h]^T  (z=128: 1024x128x128)
    launch_gemm(SSEQ, DDH, DDH,
                q,   HHD * DDH, (long)SSEQ * HHD * DDH, (long)DDH,
                W2T, DDH, (long)HHD * DDH * DDH, (long)DDH * DDH,
                ohd, HHD * DDH, (long)SSEQ * HHD * DDH, (long)DDH,
                BB * HHD, HHD, nullptr, 1);

    // 17) out = out_hd @ w_o^T + b_o  (4096 x 4096 x 4096)
    launch_gemm(NTOK, IDIM, IDIM, ohd, IDIM, 0, 0, w_o, IDIM, 0, 0,
                out, IDIM, 0, 0, 1, 1, b_o, 0);
}